// round 8
// baseline (speedup 1.0000x reference)
#include <cuda_runtime.h>
#include <cstdint>

#define NN    8192
#define FIN   128
#define FOUT  64
#define ALPHA 0.2f
#define LOG2E 1.4426950408889634f

#define TI    128
#define SPLIT 4
#define JH    (NN/SPLIT)   // 2048
#define KC    64
#define NCH   (JH/KC)      // 32

#define A_STRIDE 72        // ints per A row (64 + pad)
#define B_STRIDE 72        // halves per B row (64 + pad)
#define A_BUF  (TI*A_STRIDE*4)          // 36864
#define B_BUF  (FOUT*B_STRIDE*2)        // 9216
#define EF_BUF (KC*8)                   // 512
#define STAGE_BYTES (A_BUF + B_BUF + EF_BUF)   // 46592
#define GAT_SMEM (2*STAGE_BYTES + 256)

// ---------------- device scratch ----------------
__device__ uint16_t g_hT16[(size_t)FOUT * NN];  // h^T fp16 [f][node]
__device__ float2 g_EF1[NN];                    // {exp2(s1'), exp2(0.2 s1')}
__device__ float2 g_EF2[NN];
__device__ float  g_part[SPLIT][(size_t)NN * FOUT];
__device__ float  g_wsum[SPLIT][NN];
__device__ int    g_cnt[NN / TI];

// ---------------- helpers ----------------
__device__ __forceinline__ float ex2f(float x) {
    float r; asm("ex2.approx.ftz.f32 %0, %1;" : "=f"(r) : "f"(x)); return r;
}
__device__ __forceinline__ uint32_t smem_u32(const void* p) {
    uint32_t a;
    asm("{ .reg .u64 t; cvta.to.shared.u64 t, %1; cvt.u32.u64 %0, t; }" : "=r"(a) : "l"(p));
    return a;
}
// f32 -> fp16 bits (no cuda_fp16.h dependency)
__device__ __forceinline__ uint16_t f2h(float x) {
    uint16_t r; asm("cvt.rn.f16.f32 %0, %1;" : "=h"(r) : "f"(x)); return r;
}
// pack (lo, hi) -> f16x2 (first src goes to HIGH half)
__device__ __forceinline__ uint32_t pkh2(float lo, float hi) {
    uint32_t r; asm("cvt.rn.f16x2.f32 %0, %1, %2;" : "=r"(r) : "f"(hi), "f"(lo)); return r;
}

#define CP16(dst, src) \
    asm volatile("cp.async.cg.shared.global [%0], [%1], 16;" :: "r"(dst), "l"(src) : "memory")
#define CP_COMMIT() asm volatile("cp.async.commit_group;" ::: "memory")
#define CP_WAIT0()  asm volatile("cp.async.wait_group 0;" ::: "memory")

__device__ __forceinline__ uint32_t lds_u32(uint32_t a) {
    uint32_t v; asm volatile("ld.shared.b32 %0, [%1];" : "=r"(v) : "r"(a)); return v;
}
__device__ __forceinline__ int2 lds_s64(uint32_t a) {
    int2 v; asm volatile("ld.shared.v2.u32 {%0,%1}, [%2];" : "=r"(v.x), "=r"(v.y) : "r"(a)); return v;
}
__device__ __forceinline__ float4 lds_f4(uint32_t a) {
    float4 v;
    asm volatile("ld.shared.v4.f32 {%0,%1,%2,%3}, [%4];"
                 : "=f"(v.x), "=f"(v.y), "=f"(v.z), "=f"(v.w) : "r"(a));
    return v;
}

#define MMA_F16(c, a0, a1, a2, a3, b0, b1) \
    asm volatile("mma.sync.aligned.m16n8k16.row.col.f32.f16.f16.f32 " \
        "{%0,%1,%2,%3}, {%4,%5,%6,%7}, {%8,%9}, {%0,%1,%2,%3};" \
        : "+f"((c)[0]), "+f"((c)[1]), "+f"((c)[2]), "+f"((c)[3]) \
        : "r"(a0), "r"(a1), "r"(a2), "r"(a3), "r"(b0), "r"(b1))

// ===================== K1: projection + node tables + counter reset =====================
__global__ __launch_bounds__(256) void k_proj(const float* __restrict__ X,
                                              const float* __restrict__ W,
                                              const float* __restrict__ a1,
                                              const float* __restrict__ a2) {
    __shared__ float Ws[FIN * FOUT];          // [k][f]
    __shared__ float Xs[FIN * 17];            // [k][row]
    __shared__ uint16_t hTs[FOUT * 20];       // fp16 staging [f][row], stride 20

    const int tid = threadIdx.x;
    const int i0 = blockIdx.x * 16;

    if (blockIdx.x == 0 && tid < NN / TI) g_cnt[tid] = 0;

    {   // W fill
        const float4* W4 = (const float4*)W;
        float4* Ws4 = (float4*)Ws;
#pragma unroll
        for (int k = 0; k < 8; k++) Ws4[tid + k * 256] = W4[tid + k * 256];
    }
    {   // X transpose fill
        const int row = tid & 15;
        const int q0 = tid >> 4;
#pragma unroll
        for (int m = 0; m < 2; m++) {
            const int q = q0 + 16 * m;
            const float4 v = *(const float4*)(X + (size_t)(i0 + row) * FIN + 4 * q);
            Xs[(4 * q + 0) * 17 + row] = v.x;
            Xs[(4 * q + 1) * 17 + row] = v.y;
            Xs[(4 * q + 2) * 17 + row] = v.z;
            Xs[(4 * q + 3) * 17 + row] = v.w;
        }
    }
    __syncthreads();

    const int rg = tid >> 4;
    const int cg = tid & 15;
    const float4* Ws4 = (const float4*)Ws;

    float aA[4] = {0.f, 0.f, 0.f, 0.f}, aB[4] = {0.f, 0.f, 0.f, 0.f};
#pragma unroll 8
    for (int k = 0; k < FIN; k += 2) {
        const float x0 = Xs[k * 17 + rg];
        const float x1 = Xs[(k + 1) * 17 + rg];
        const float4 w0 = Ws4[k * 16 + cg];
        const float4 w1 = Ws4[(k + 1) * 16 + cg];
        aA[0] += x0 * w0.x; aA[1] += x0 * w0.y; aA[2] += x0 * w0.z; aA[3] += x0 * w0.w;
        aB[0] += x1 * w1.x; aB[1] += x1 * w1.y; aB[2] += x1 * w1.z; aB[3] += x1 * w1.w;
    }
    float acc[4];
#pragma unroll
    for (int c = 0; c < 4; c++) acc[c] = aA[c] + aB[c];

    // stage fp16 h transposed: hTs[f][row]
#pragma unroll
    for (int c = 0; c < 4; c++) {
        hTs[(4 * cg + c) * 20 + rg] = f2h(acc[c]);
    }

    const float4 a1v = ((const float4*)a1)[cg];
    const float4 a2v = ((const float4*)a2)[cg];
    float v1 = acc[0] * a1v.x + acc[1] * a1v.y + acc[2] * a1v.z + acc[3] * a1v.w;
    float v2 = acc[0] * a2v.x + acc[1] * a2v.y + acc[2] * a2v.z + acc[3] * a2v.w;
#pragma unroll
    for (int s = 8; s > 0; s >>= 1) {
        v1 += __shfl_xor_sync(0xffffffffu, v1, s, 16);
        v2 += __shfl_xor_sync(0xffffffffu, v2, s, 16);
    }
    if (cg == 0) {
        const float s1L = v1 * LOG2E;
        const float s2L = v2 * LOG2E;
        const int node = i0 + rg;
        g_EF1[node] = make_float2(ex2f(s1L), ex2f(ALPHA * s1L));
        g_EF2[node] = make_float2(ex2f(s2L), ex2f(ALPHA * s2L));
    }
    __syncthreads();

    // coalesced hT write-out: thread -> (f = tid>>2, 4 nodes at seg = tid&3)
    {
        const int f = tid >> 2;
        const int sg = tid & 3;
        const uint2 v = *(const uint2*)&hTs[f * 20 + 4 * sg];
        *(uint2*)(g_hT16 + (size_t)f * NN + i0 + 4 * sg) = v;
    }
}

// ===================== K2: fused masked softmax + aggregation + combine =====================
__global__ __launch_bounds__(256, 2) void k_gat(const int* __restrict__ A,
                                                float* __restrict__ out) {
    extern __shared__ char sm[];
    const uint32_t sb0 = smem_u32(sm);
    const uint32_t sb = (sb0 + 127u) & ~127u;

    const int tid  = threadIdx.x;
    const int wid  = tid >> 5;
    const int lane = tid & 31;
    const int qr   = lane >> 2;
    const int qc   = lane & 3;
    const int mg   = wid >> 1;
    const int ng   = wid & 1;
    const int ib   = blockIdx.x >> 2;
    const int sk   = blockIdx.x & 3;
    const int i0   = ib * TI;
    const int j0   = sk * JH;

    // fill mappings
    const int arow = tid >> 4;               // 0..15
    const int aseg = tid & 15;               // 0..15 (16B units of A row)
    const int bf   = tid >> 2;               // 0..63
    const int bsg  = tid & 3;                // 0..3
    const int* aSrcBase = A + (size_t)i0 * NN + j0;
    const uint16_t* hSrcBase = g_hT16 + j0;

    float2 ef1[4];
#pragma unroll
    for (int k = 0; k < 4; k++) ef1[k] = g_EF1[i0 + mg * 32 + qr + 8 * k];

    float acc[2][4][4];
#pragma unroll
    for (int mt = 0; mt < 2; mt++)
#pragma unroll
        for (int nt = 0; nt < 4; nt++)
#pragma unroll
            for (int k = 0; k < 4; k++) acc[mt][nt][k] = 0.f;
    float wsum[4] = {0.f, 0.f, 0.f, 0.f};

#define ISSUE(T) do {                                                              \
        const uint32_t _base = sb + (uint32_t)(((T) & 1) * STAGE_BYTES);           \
        const int _jo = (T) * KC;                                                  \
        _Pragma("unroll")                                                          \
        for (int k = 0; k < 8; k++) {                                              \
            const int r = arow + 16 * k;                                           \
            CP16(_base + (uint32_t)(r * A_STRIDE + aseg * 4) * 4,                  \
                 aSrcBase + (size_t)r * NN + _jo + aseg * 4);                      \
        }                                                                          \
        _Pragma("unroll")                                                          \
        for (int m = 0; m < 2; m++) {                                              \
            const int sg = bsg + 4 * m;                                            \
            CP16(_base + A_BUF + (uint32_t)(bf * B_STRIDE + sg * 8) * 2,           \
                 hSrcBase + (size_t)bf * NN + _jo + sg * 8);                       \
        }                                                                          \
        if (tid < 32)                                                              \
            CP16(_base + A_BUF + B_BUF + (uint32_t)tid * 16,                       \
                 (const float2*)g_EF2 + j0 + _jo + tid * 2);                       \
        CP_COMMIT();                                                               \
    } while (0)

    ISSUE(0);

    for (int t = 0; t < NCH; t++) {
        CP_WAIT0();
        __syncthreads();
        if (t + 1 < NCH) ISSUE(t + 1);   // fills the other stage during compute

        const uint32_t aB = sb + (uint32_t)((t & 1) * STAGE_BYTES);
        const uint32_t bB = aB + A_BUF;
        const uint32_t eB = aB + A_BUF + B_BUF;

#pragma unroll
        for (int ks = 0; ks < 4; ks++) {
            const int j2 = 16 * ks + 2 * qc;
            const float4 efL = lds_f4(eB + (uint32_t)j2 * 8);        // E,F @ j2, j2+1
            const float4 efH = lds_f4(eB + (uint32_t)(j2 + 8) * 8);  // E,F @ j2+8, j2+9

            uint32_t b0[4], b1[4];
#pragma unroll
            for (int nt = 0; nt < 4; nt++) {
                const int f = ng * 32 + nt * 8 + qr;
                const uint32_t hb = bB + (uint32_t)(f * B_STRIDE + j2) * 2;
                b0[nt] = lds_u32(hb);
                b1[nt] = lds_u32(hb + 16);
            }

#pragma unroll
            for (int mt = 0; mt < 2; mt++) {
                const int r0 = mg * 32 + mt * 16 + qr;
                const uint32_t ab0 = aB + (uint32_t)(r0 * A_STRIDE + j2) * 4;
                const uint32_t ab1 = ab0 + (uint32_t)(8 * A_STRIDE) * 4;
                const int2 lo0 = lds_s64(ab0);
                const int2 hi0 = lds_s64(ab0 + 32);
                const int2 lo1 = lds_s64(ab1);
                const int2 hi1 = lds_s64(ab1 + 32);

                const float2 e1a = ef1[2 * mt];
                const float2 e1b = ef1[2 * mt + 1];
                float w00 = fmaxf(e1a.x * efL.x, e1a.y * efL.y); if (lo0.x <= 0) w00 = 0.f;
                float w01 = fmaxf(e1a.x * efL.z, e1a.y * efL.w); if (lo0.y <= 0) w01 = 0.f;
                float w02 = fmaxf(e1a.x * efH.x, e1a.y * efH.y); if (hi0.x <= 0) w02 = 0.f;
                float w03 = fmaxf(e1a.x * efH.z, e1a.y * efH.w); if (hi0.y <= 0) w03 = 0.f;
                float w10 = fmaxf(e1b.x * efL.x, e1b.y * efL.y); if (lo1.x <= 0) w10 = 0.f;
                float w11 = fmaxf(e1b.x * efL.z, e1b.y * efL.w); if (lo1.y <= 0) w11 = 0.f;
                float w12 = fmaxf(e1b.x * efH.x, e1b.y * efH.y); if (hi1.x <= 0) w12 = 0.f;
                float w13 = fmaxf(e1b.x * efH.z, e1b.y * efH.w); if (hi1.y <= 0) w13 = 0.f;

                wsum[2 * mt]     += (w00 + w01) + (w02 + w03);
                wsum[2 * mt + 1] += (w10 + w11) + (w12 + w13);

                const uint32_t a0 = pkh2(w00, w01);
                const uint32_t a1 = pkh2(w10, w11);
                const uint32_t a2 = pkh2(w02, w03);
                const uint32_t a3 = pkh2(w12, w13);
#pragma unroll
                for (int nt = 0; nt < 4; nt++)
                    MMA_F16(acc[mt][nt], a0, a1, a2, a3, b0[nt], b1[nt]);
            }
        }
        __syncthreads();   // all warps done with stage (t&1) before it is refilled at t+2
    }

    // ---- epilogue: store partials ----
#pragma unroll
    for (int k = 0; k < 4; k++) {
        wsum[k] += __shfl_xor_sync(0xffffffffu, wsum[k], 1);
        wsum[k] += __shfl_xor_sync(0xffffffffu, wsum[k], 2);
    }
    if (ng == 0 && qc == 0) {
#pragma unroll
        for (int k = 0; k < 4; k++)
            g_wsum[sk][i0 + mg * 32 + qr + 8 * k] = wsum[k];
    }
#pragma unroll
    for (int mt = 0; mt < 2; mt++) {
        float* pr0 = &g_part[sk][(size_t)(i0 + mg * 32 + mt * 16 + qr) * FOUT];
        float* pr1 = &g_part[sk][(size_t)(i0 + mg * 32 + mt * 16 + qr + 8) * FOUT];
#pragma unroll
        for (int nt = 0; nt < 4; nt++) {
            const int c0 = ng * 32 + nt * 8 + 2 * qc;
            *(float2*)(pr0 + c0) = make_float2(acc[mt][nt][0], acc[mt][nt][1]);
            *(float2*)(pr1 + c0) = make_float2(acc[mt][nt][2], acc[mt][nt][3]);
        }
    }

    // ---- last split-K CTA for this i-block combines and divides ----
    __threadfence();
    __shared__ int isLast;
    if (tid == 0) isLast = (atomicAdd(&g_cnt[ib], 1) == SPLIT - 1) ? 1 : 0;
    __syncthreads();
    if (isLast) {
        __threadfence();
#pragma unroll
        for (int k = 0; k < 8; k++) {
            const int idx4 = tid + k * 256;
            const int row = idx4 >> 4;
            const size_t e = (size_t)(i0 + row) * FOUT + (idx4 & 15) * 4;
            float4 s = *(const float4*)&g_part[0][e];
            float den = g_wsum[0][i0 + row];
#pragma unroll
            for (int p = 1; p < SPLIT; p++) {
                const float4 pp = *(const float4*)&g_part[p][e];
                s.x += pp.x; s.y += pp.y; s.z += pp.z; s.w += pp.w;
                den += g_wsum[p][i0 + row];
            }
            const float inv = 1.0f / den;
            *(float4*)(out + e) = make_float4(s.x * inv, s.y * inv, s.z * inv, s.w * inv);
        }
    }
}

extern "C" void kernel_launch(void* const* d_in, const int* in_sizes, int n_in,
                              void* d_out, int out_size) {
    const float* X  = (const float*)d_in[0];
    const int*   A  = (const int*)d_in[1];
    const float* W  = (const float*)d_in[2];
    const float* a1 = (const float*)d_in[3];
    const float* a2 = (const float*)d_in[4];
    float* out = (float*)d_out;

    cudaFuncSetAttribute(k_gat, cudaFuncAttributeMaxDynamicSharedMemorySize, GAT_SMEM);

    k_proj<<<NN / 16, 256>>>(X, W, a1, a2);
    k_gat<<<(NN / TI) * SPLIT, 256, GAT_SMEM>>>(A, out);
}

// round 9
// speedup vs baseline: 1.3802x; 1.3802x over previous
#include <cuda_runtime.h>
#include <cstdint>

#define NN    8192
#define FIN   128
#define FOUT  64
#define ALPHA 0.2f
#define LOG2E 1.4426950408889634f

#define TI    128
#define SPLIT 4
#define JH    (NN/SPLIT)   // 2048
#define KC    32
#define NCH   (JH/KC)      // 64
#define NSTAGE 3

#define A_STRIDE 40        // ints per A row (32 + pad) -> 160B
#define B_STRIDE 40        // halves per B row (32 + pad) -> 80B
#define A_BUF  (TI*A_STRIDE*4)          // 20480
#define B_BUF  (FOUT*B_STRIDE*2)        // 5120
#define EF_BUF 256                      // 128 used (KC/2 x uint2)
#define STAGE_BYTES (A_BUF + B_BUF + EF_BUF)   // 25856
#define GAT_SMEM (NSTAGE*STAGE_BYTES + 256)

// ---------------- device scratch ----------------
__device__ __align__(256) uint16_t g_hT16[(size_t)FOUT * NN];  // h^T fp16 [f][node]
__device__ __align__(256) uint2 g_EF1p[NN];     // {E1 dup f16x2, F1 dup f16x2}
__device__ __align__(256) uint2 g_E2Fp[NN/2];   // {E2 pair f16x2, F2 pair f16x2} per node-pair
__device__ float  g_part[SPLIT][(size_t)NN * FOUT];
__device__ float  g_wsum[SPLIT][NN];
__device__ int    g_cnt[NN / TI];

// ---------------- helpers ----------------
__device__ __forceinline__ float ex2f(float x) {
    float r; asm("ex2.approx.ftz.f32 %0, %1;" : "=f"(r) : "f"(x)); return r;
}
__device__ __forceinline__ uint32_t smem_u32(const void* p) {
    uint32_t a;
    asm("{ .reg .u64 t; cvta.to.shared.u64 t, %1; cvt.u32.u64 %0, t; }" : "=r"(a) : "l"(p));
    return a;
}
__device__ __forceinline__ uint16_t f2h(float x) {
    uint16_t r; asm("cvt.rn.f16.f32 %0, %1;" : "=h"(r) : "f"(x)); return r;
}
// pack (lo, hi) -> f16x2 (first asm src fills HIGH half)
__device__ __forceinline__ uint32_t pkh2(float lo, float hi) {
    uint32_t r; asm("cvt.rn.f16x2.f32 %0, %1, %2;" : "=r"(r) : "f"(hi), "f"(lo)); return r;
}
__device__ __forceinline__ uint32_t hmul2(uint32_t a, uint32_t b) {
    uint32_t r; asm("mul.f16x2 %0, %1, %2;" : "=r"(r) : "r"(a), "r"(b)); return r;
}
__device__ __forceinline__ uint32_t hmax2(uint32_t a, uint32_t b) {
    uint32_t r; asm("max.f16x2 %0, %1, %2;" : "=r"(r) : "r"(a), "r"(b)); return r;
}
// masked w pair: mask = {1.0h if ax, 1.0h if ay} built by integer math (a in {0,1})
__device__ __forceinline__ uint32_t wpair(uint32_t e1E, uint32_t e1F,
                                          uint32_t e2, uint32_t f2,
                                          int ax, int ay) {
    const uint32_t m = (uint32_t)ax * 0x3C00u + (uint32_t)ay * 0x3C000000u;
    return hmul2(hmax2(hmul2(e1E, e2), hmul2(e1F, f2)), m);
}

#define CP16(dst, src) \
    asm volatile("cp.async.cg.shared.global [%0], [%1], 16;" :: "r"(dst), "l"(src) : "memory")
#define CP_COMMIT() asm volatile("cp.async.commit_group;" ::: "memory")
#define CP_WAIT1()  asm volatile("cp.async.wait_group 1;" ::: "memory")
#define CP_WAIT0()  asm volatile("cp.async.wait_group 0;" ::: "memory")

__device__ __forceinline__ uint32_t lds_u32(uint32_t a) {
    uint32_t v; asm volatile("ld.shared.b32 %0, [%1];" : "=r"(v) : "r"(a)); return v;
}
__device__ __forceinline__ int2 lds_s64(uint32_t a) {
    int2 v; asm volatile("ld.shared.v2.u32 {%0,%1}, [%2];" : "=r"(v.x), "=r"(v.y) : "r"(a)); return v;
}
__device__ __forceinline__ uint2 lds_u64(uint32_t a) {
    uint2 v; asm volatile("ld.shared.v2.u32 {%0,%1}, [%2];" : "=r"(v.x), "=r"(v.y) : "r"(a)); return v;
}

#define MMA_F16(c, a0, a1, a2, a3, b0, b1) \
    asm volatile("mma.sync.aligned.m16n8k16.row.col.f32.f16.f16.f32 " \
        "{%0,%1,%2,%3}, {%4,%5,%6,%7}, {%8,%9}, {%0,%1,%2,%3};" \
        : "+f"((c)[0]), "+f"((c)[1]), "+f"((c)[2]), "+f"((c)[3]) \
        : "r"(a0), "r"(a1), "r"(a2), "r"(a3), "r"(b0), "r"(b1))

// ===================== K1: projection + node tables + counter reset =====================
__global__ __launch_bounds__(256) void k_proj(const float* __restrict__ X,
                                              const float* __restrict__ W,
                                              const float* __restrict__ a1,
                                              const float* __restrict__ a2) {
    __shared__ float Ws[FIN * FOUT];
    __shared__ float Xs[FIN * 17];
    __shared__ uint16_t hTs[FOUT * 20];

    const int tid = threadIdx.x;
    const int i0 = blockIdx.x * 16;

    if (blockIdx.x == 0 && tid < NN / TI) g_cnt[tid] = 0;

    {   // W fill
        const float4* W4 = (const float4*)W;
        float4* Ws4 = (float4*)Ws;
#pragma unroll
        for (int k = 0; k < 8; k++) Ws4[tid + k * 256] = W4[tid + k * 256];
    }
    {   // X transpose fill
        const int row = tid & 15;
        const int q0 = tid >> 4;
#pragma unroll
        for (int m = 0; m < 2; m++) {
            const int q = q0 + 16 * m;
            const float4 v = *(const float4*)(X + (size_t)(i0 + row) * FIN + 4 * q);
            Xs[(4 * q + 0) * 17 + row] = v.x;
            Xs[(4 * q + 1) * 17 + row] = v.y;
            Xs[(4 * q + 2) * 17 + row] = v.z;
            Xs[(4 * q + 3) * 17 + row] = v.w;
        }
    }
    __syncthreads();

    const int rg = tid >> 4;
    const int cg = tid & 15;
    const float4* Ws4 = (const float4*)Ws;

    float aA[4] = {0.f, 0.f, 0.f, 0.f}, aB[4] = {0.f, 0.f, 0.f, 0.f};
#pragma unroll 8
    for (int k = 0; k < FIN; k += 2) {
        const float x0 = Xs[k * 17 + rg];
        const float x1 = Xs[(k + 1) * 17 + rg];
        const float4 w0 = Ws4[k * 16 + cg];
        const float4 w1 = Ws4[(k + 1) * 16 + cg];
        aA[0] += x0 * w0.x; aA[1] += x0 * w0.y; aA[2] += x0 * w0.z; aA[3] += x0 * w0.w;
        aB[0] += x1 * w1.x; aB[1] += x1 * w1.y; aB[2] += x1 * w1.z; aB[3] += x1 * w1.w;
    }
    float acc[4];
#pragma unroll
    for (int c = 0; c < 4; c++) acc[c] = aA[c] + aB[c];

    // stage fp16 h transposed: hTs[f][row]
#pragma unroll
    for (int c = 0; c < 4; c++) hTs[(4 * cg + c) * 20 + rg] = f2h(acc[c]);

    const float4 a1v = ((const float4*)a1)[cg];
    const float4 a2v = ((const float4*)a2)[cg];
    float v1 = acc[0] * a1v.x + acc[1] * a1v.y + acc[2] * a1v.z + acc[3] * a1v.w;
    float v2 = acc[0] * a2v.x + acc[1] * a2v.y + acc[2] * a2v.z + acc[3] * a2v.w;
#pragma unroll
    for (int s = 8; s > 0; s >>= 1) {
        v1 += __shfl_xor_sync(0xffffffffu, v1, s, 16);
        v2 += __shfl_xor_sync(0xffffffffu, v2, s, 16);
    }

    // node tables (valid values live at cg==0 lanes: lanes 0 and 16)
    const float s1L = v1 * LOG2E;
    const float s2L = v2 * LOG2E;
    const float E1 = ex2f(s1L), F1 = ex2f(ALPHA * s1L);
    const float E2 = ex2f(s2L), F2 = ex2f(ALPHA * s2L);
    const float E2o = __shfl_xor_sync(0xffffffffu, E2, 16);
    const float F2o = __shfl_xor_sync(0xffffffffu, F2, 16);
    if (cg == 0) {
        g_EF1p[i0 + rg] = make_uint2(pkh2(E1, E1), pkh2(F1, F1));
        if ((tid & 31) == 0)  // even rg lane: pack (even, odd) node pair
            g_E2Fp[(i0 + rg) >> 1] = make_uint2(pkh2(E2, E2o), pkh2(F2, F2o));
    }
    __syncthreads();

    // coalesced hT write-out
    {
        const int f = tid >> 2;
        const int sg = tid & 3;
        const uint2 v = *(const uint2*)&hTs[f * 20 + 4 * sg];
        *(uint2*)(g_hT16 + (size_t)f * NN + i0 + 4 * sg) = v;
    }
}

// ===================== K2: fused masked softmax + aggregation + combine =====================
__global__ __launch_bounds__(256, 2) void k_gat(const int* __restrict__ A,
                                                float* __restrict__ out) {
    extern __shared__ char sm[];
    const uint32_t sb0 = smem_u32(sm);
    const uint32_t sb = (sb0 + 127u) & ~127u;

    const int tid  = threadIdx.x;
    const int wid  = tid >> 5;
    const int lane = tid & 31;
    const int qr   = lane >> 2;
    const int qc   = lane & 3;
    const int mg   = wid >> 1;
    const int ng   = wid & 1;
    const int ib   = blockIdx.x >> 2;
    const int sk   = blockIdx.x & 3;
    const int i0   = ib * TI;
    const int j0   = sk * JH;

    // fill mappings
    const int arow = tid >> 1;               // 0..127
    const int asg0 = (tid & 1) * 4;          // 16B segment base (of 8)
    const int bf   = tid >> 2;               // 0..63
    const int bsg  = tid & 3;                // 0..3
    const int* aSrcBase = A + (size_t)i0 * NN + j0;
    const uint16_t* hSrcBase = g_hT16 + j0;

    uint32_t e1E[4], e1F[4];
#pragma unroll
    for (int k = 0; k < 4; k++) {
        const uint2 v = g_EF1p[i0 + mg * 32 + qr + 8 * k];
        e1E[k] = v.x; e1F[k] = v.y;
    }

    float acc[2][4][4];
    float accO[2][4];
#pragma unroll
    for (int mt = 0; mt < 2; mt++) {
#pragma unroll
        for (int nt = 0; nt < 4; nt++)
#pragma unroll
            for (int k = 0; k < 4; k++) acc[mt][nt][k] = 0.f;
#pragma unroll
        for (int k = 0; k < 4; k++) accO[mt][k] = 0.f;
    }
    const uint32_t kOnes = 0x3C003C00u;

#define ISSUE(T) do {                                                              \
        const uint32_t _base = sb + (uint32_t)(((T) % NSTAGE) * STAGE_BYTES);      \
        const int _jo = (T) * KC;                                                  \
        _Pragma("unroll")                                                          \
        for (int k = 0; k < 4; k++) {                                              \
            const int sg = asg0 + k;                                               \
            CP16(_base + (uint32_t)(arow * A_STRIDE + sg * 4) * 4,                 \
                 aSrcBase + (size_t)arow * NN + _jo + sg * 4);                     \
        }                                                                          \
        CP16(_base + A_BUF + (uint32_t)(bf * B_STRIDE + bsg * 8) * 2,              \
             hSrcBase + (size_t)bf * NN + _jo + bsg * 8);                          \
        if (tid < 8)                                                               \
            CP16(_base + A_BUF + B_BUF + (uint32_t)tid * 16,                       \
                 g_E2Fp + ((j0 + _jo) >> 1) + tid * 2);                            \
        CP_COMMIT();                                                               \
    } while (0)

    ISSUE(0);
    ISSUE(1);

    for (int t = 0; t < NCH; t++) {
        if (t + 1 < NCH) CP_WAIT1(); else CP_WAIT0();
        __syncthreads();
        if (t + 2 < NCH) ISSUE(t + 2);

        const uint32_t aB = sb + (uint32_t)((t % NSTAGE) * STAGE_BYTES);
        const uint32_t bB = aB + A_BUF;
        const uint32_t eB = aB + A_BUF + B_BUF;

#pragma unroll
        for (int ks = 0; ks < 2; ks++) {
            const int j2 = 16 * ks + 2 * qc;
            const uint2 efL = lds_u64(eB + (uint32_t)(j2 >> 1) * 8);        // {E2p,F2p} @ j2
            const uint2 efH = lds_u64(eB + (uint32_t)((j2 + 8) >> 1) * 8);  // @ j2+8

            uint32_t b0[4], b1[4];
#pragma unroll
            for (int nt = 0; nt < 4; nt++) {
                const int f = ng * 32 + nt * 8 + qr;
                const uint32_t hb = bB + (uint32_t)(f * B_STRIDE + j2) * 2;
                b0[nt] = lds_u32(hb);
                b1[nt] = lds_u32(hb + 16);
            }

#pragma unroll
            for (int mt = 0; mt < 2; mt++) {
                const int r0 = mg * 32 + mt * 16 + qr;
                const uint32_t ab = aB + (uint32_t)(r0 * A_STRIDE + j2) * 4;
                const int2 Al0 = lds_s64(ab);                                   // (r0, j2)
                const int2 Ah0 = lds_s64(ab + 32);                              // (r0, j2+8)
                const int2 Al1 = lds_s64(ab + (uint32_t)(8 * A_STRIDE) * 4);    // (r0+8, j2)
                const int2 Ah1 = lds_s64(ab + (uint32_t)(8 * A_STRIDE) * 4 + 32);

                const uint32_t a0 = wpair(e1E[2 * mt],     e1F[2 * mt],     efL.x, efL.y, Al0.x, Al0.y);
                const uint32_t a1 = wpair(e1E[2 * mt + 1], e1F[2 * mt + 1], efL.x, efL.y, Al1.x, Al1.y);
                const uint32_t a2 = wpair(e1E[2 * mt],     e1F[2 * mt],     efH.x, efH.y, Ah0.x, Ah0.y);
                const uint32_t a3 = wpair(e1E[2 * mt + 1], e1F[2 * mt + 1], efH.x, efH.y, Ah1.x, Ah1.y);

#pragma unroll
                for (int nt = 0; nt < 4; nt++)
                    MMA_F16(acc[mt][nt], a0, a1, a2, a3, b0[nt], b1[nt]);
                MMA_F16(accO[mt], a0, a1, a2, a3, kOnes, kOnes);   // row sums
            }
        }
    }

    // ---- epilogue: wsum directly from ones-MMA accumulators ----
    if (ng == 0 && qc == 0) {
        g_wsum[sk][i0 + mg * 32 + qr]      = accO[0][0];
        g_wsum[sk][i0 + mg * 32 + qr + 8]  = accO[0][2];
        g_wsum[sk][i0 + mg * 32 + qr + 16] = accO[1][0];
        g_wsum[sk][i0 + mg * 32 + qr + 24] = accO[1][2];
    }
#pragma unroll
    for (int mt = 0; mt < 2; mt++) {
        float* pr0 = &g_part[sk][(size_t)(i0 + mg * 32 + mt * 16 + qr) * FOUT];
        float* pr1 = &g_part[sk][(size_t)(i0 + mg * 32 + mt * 16 + qr + 8) * FOUT];
#pragma unroll
        for (int nt = 0; nt < 4; nt++) {
            const int c0 = ng * 32 + nt * 8 + 2 * qc;
            *(float2*)(pr0 + c0) = make_float2(acc[mt][nt][0], acc[mt][nt][1]);
            *(float2*)(pr1 + c0) = make_float2(acc[mt][nt][2], acc[mt][nt][3]);
        }
    }

    // ---- last split-K CTA for this i-block combines and divides ----
    __threadfence();
    __shared__ int isLast;
    if (tid == 0) isLast = (atomicAdd(&g_cnt[ib], 1) == SPLIT - 1) ? 1 : 0;
    __syncthreads();
    if (isLast) {
        __threadfence();
#pragma unroll
        for (int k = 0; k < 8; k++) {
            const int idx4 = tid + k * 256;
            const int row = idx4 >> 4;
            const size_t e = (size_t)(i0 + row) * FOUT + (idx4 & 15) * 4;
            float4 s = *(const float4*)&g_part[0][e];
            float den = g_wsum[0][i0 + row];
#pragma unroll
            for (int p = 1; p < SPLIT; p++) {
                const float4 pp = *(const float4*)&g_part[p][e];
                s.x += pp.x; s.y += pp.y; s.z += pp.z; s.w += pp.w;
                den += g_wsum[p][i0 + row];
            }
            const float inv = 1.0f / den;
            *(float4*)(out + e) = make_float4(s.x * inv, s.y * inv, s.z * inv, s.w * inv);
        }
    }
}

extern "C" void kernel_launch(void* const* d_in, const int* in_sizes, int n_in,
                              void* d_out, int out_size) {
    const float* X  = (const float*)d_in[0];
    const int*   A  = (const int*)d_in[1];
    const float* W  = (const float*)d_in[2];
    const float* a1 = (const float*)d_in[3];
    const float* a2 = (const float*)d_in[4];
    float* out = (float*)d_out;

    cudaFuncSetAttribute(k_gat, cudaFuncAttributeMaxDynamicSharedMemorySize, GAT_SMEM);

    k_proj<<<NN / 16, 256>>>(X, W, a1, a2);
    k_gat<<<(NN / TI) * SPLIT, 256, GAT_SMEM>>>(A, out);
}

// round 10
// speedup vs baseline: 1.6939x; 1.2273x over previous
#include <cuda_runtime.h>
#include <cstdint>

#define NN    8192
#define FIN   128
#define FOUT  64
#define ALPHA 0.2f
#define LOG2E 1.4426950408889634f

#define TI    128
#define SPLIT 2
#define JH    (NN/SPLIT)   // 4096
#define KC    32
#define NCH   (JH/KC)      // 128
#define NSTAGE 8

#define NTHREADS 320       // 8 consumer warps + 2 producer warps

#define A_STRIDE 40        // ints per A row (32 + pad) -> 160B
#define B_STRIDE 40        // halves per B row (32 + pad) -> 80B
#define A_BUF  (TI*A_STRIDE*4)          // 20480
#define B_BUF  (FOUT*B_STRIDE*2)        // 5120
#define EF_BUF 256                      // 128 used
#define STAGE_BYTES (A_BUF + B_BUF + EF_BUF)   // 25856
#define MBAR_OFF   (NSTAGE*STAGE_BYTES)        // 206848
#define GAT_SMEM   (MBAR_OFF + NSTAGE*16 + 256)

// ---------------- device scratch ----------------
__device__ __align__(256) uint16_t g_hT16[(size_t)FOUT * NN];  // h^T fp16 [f][node]
__device__ __align__(256) uint2 g_EF1p[NN];     // {E1 dup f16x2, F1 dup f16x2}
__device__ __align__(256) uint2 g_E2Fp[NN/2];   // {E2 pair f16x2, F2 pair f16x2}
__device__ float  g_part[SPLIT][(size_t)NN * FOUT];
__device__ float  g_wsum[SPLIT][NN];
__device__ int    g_cnt[NN / TI];

// ---------------- helpers ----------------
__device__ __forceinline__ float ex2f(float x) {
    float r; asm("ex2.approx.ftz.f32 %0, %1;" : "=f"(r) : "f"(x)); return r;
}
__device__ __forceinline__ uint32_t smem_u32(const void* p) {
    uint32_t a;
    asm("{ .reg .u64 t; cvta.to.shared.u64 t, %1; cvt.u32.u64 %0, t; }" : "=r"(a) : "l"(p));
    return a;
}
__device__ __forceinline__ uint16_t f2h(float x) {
    uint16_t r; asm("cvt.rn.f16.f32 %0, %1;" : "=h"(r) : "f"(x)); return r;
}
__device__ __forceinline__ uint32_t pkh2(float lo, float hi) {
    uint32_t r; asm("cvt.rn.f16x2.f32 %0, %1, %2;" : "=r"(r) : "f"(hi), "f"(lo)); return r;
}
__device__ __forceinline__ uint32_t hmul2(uint32_t a, uint32_t b) {
    uint32_t r; asm("mul.f16x2 %0, %1, %2;" : "=r"(r) : "r"(a), "r"(b)); return r;
}
__device__ __forceinline__ uint32_t hmax2(uint32_t a, uint32_t b) {
    uint32_t r; asm("max.f16x2 %0, %1, %2;" : "=r"(r) : "r"(a), "r"(b)); return r;
}
__device__ __forceinline__ uint32_t wpair(uint32_t e1E, uint32_t e1F,
                                          uint32_t e2, uint32_t f2,
                                          int ax, int ay) {
    const uint32_t m = (uint32_t)ax * 0x3C00u + (uint32_t)ay * 0x3C000000u;
    return hmul2(hmax2(hmul2(e1E, e2), hmul2(e1F, f2)), m);
}

#define CP16(dst, src) \
    asm volatile("cp.async.cg.shared.global [%0], [%1], 16;" :: "r"(dst), "l"(src) : "memory")

// mbarrier ops
#define MBAR_INIT(mb, cnt) \
    asm volatile("mbarrier.init.shared.b64 [%0], %1;" :: "r"((uint32_t)(mb)), "r"((uint32_t)(cnt)) : "memory")
#define MBAR_ARRIVE(mb) \
    asm volatile("mbarrier.arrive.shared.b64 _, [%0];" :: "r"((uint32_t)(mb)) : "memory")
#define CPASYNC_MBAR_ARRIVE(mb) \
    asm volatile("cp.async.mbarrier.arrive.noinc.shared.b64 [%0];" :: "r"((uint32_t)(mb)) : "memory")
#define MBAR_WAIT(mb, parity) do { \
    uint32_t _m = (uint32_t)(mb); uint32_t _p = (uint32_t)(parity); uint32_t _d; \
    asm volatile("{\n\t.reg .pred p;\n\tmbarrier.try_wait.parity.shared.b64 p, [%1], %2;\n\tselp.b32 %0, 1, 0, p;\n\t}" \
        : "=r"(_d) : "r"(_m), "r"(_p) : "memory"); \
    if (!_d) { \
        asm volatile("{\n\t.reg .pred P1;\n\tWL_%=:\n\tmbarrier.try_wait.parity.shared.b64 P1, [%0], %1;\n\t@P1 bra.uni WD_%=;\n\tbra.uni WL_%=;\n\tWD_%=:\n\t}" \
            :: "r"(_m), "r"(_p) : "memory"); \
    } } while (0)

__device__ __forceinline__ uint32_t lds_u32(uint32_t a) {
    uint32_t v; asm volatile("ld.shared.b32 %0, [%1];" : "=r"(v) : "r"(a)); return v;
}
__device__ __forceinline__ int2 lds_s64(uint32_t a) {
    int2 v; asm volatile("ld.shared.v2.u32 {%0,%1}, [%2];" : "=r"(v.x), "=r"(v.y) : "r"(a)); return v;
}
__device__ __forceinline__ uint2 lds_u64(uint32_t a) {
    uint2 v; asm volatile("ld.shared.v2.u32 {%0,%1}, [%2];" : "=r"(v.x), "=r"(v.y) : "r"(a)); return v;
}

#define MMA_F16(c, a0, a1, a2, a3, b0, b1) \
    asm volatile("mma.sync.aligned.m16n8k16.row.col.f32.f16.f16.f32 " \
        "{%0,%1,%2,%3}, {%4,%5,%6,%7}, {%8,%9}, {%0,%1,%2,%3};" \
        : "+f"((c)[0]), "+f"((c)[1]), "+f"((c)[2]), "+f"((c)[3]) \
        : "r"(a0), "r"(a1), "r"(a2), "r"(a3), "r"(b0), "r"(b1))

// ===================== K1: projection + node tables + counter reset =====================
__global__ __launch_bounds__(256) void k_proj(const float* __restrict__ X,
                                              const float* __restrict__ W,
                                              const float* __restrict__ a1,
                                              const float* __restrict__ a2) {
    __shared__ float Ws[FIN * FOUT];
    __shared__ float Xs[FIN * 17];
    __shared__ uint16_t hTs[FOUT * 20];

    const int tid = threadIdx.x;
    const int i0 = blockIdx.x * 16;

    if (blockIdx.x == 0 && tid < NN / TI) g_cnt[tid] = 0;

    {
        const float4* W4 = (const float4*)W;
        float4* Ws4 = (float4*)Ws;
#pragma unroll
        for (int k = 0; k < 8; k++) Ws4[tid + k * 256] = W4[tid + k * 256];
    }
    {
        const int row = tid & 15;
        const int q0 = tid >> 4;
#pragma unroll
        for (int m = 0; m < 2; m++) {
            const int q = q0 + 16 * m;
            const float4 v = *(const float4*)(X + (size_t)(i0 + row) * FIN + 4 * q);
            Xs[(4 * q + 0) * 17 + row] = v.x;
            Xs[(4 * q + 1) * 17 + row] = v.y;
            Xs[(4 * q + 2) * 17 + row] = v.z;
            Xs[(4 * q + 3) * 17 + row] = v.w;
        }
    }
    __syncthreads();

    const int rg = tid >> 4;
    const int cg = tid & 15;
    const float4* Ws4 = (const float4*)Ws;

    float aA[4] = {0.f, 0.f, 0.f, 0.f}, aB[4] = {0.f, 0.f, 0.f, 0.f};
#pragma unroll 8
    for (int k = 0; k < FIN; k += 2) {
        const float x0 = Xs[k * 17 + rg];
        const float x1 = Xs[(k + 1) * 17 + rg];
        const float4 w0 = Ws4[k * 16 + cg];
        const float4 w1 = Ws4[(k + 1) * 16 + cg];
        aA[0] += x0 * w0.x; aA[1] += x0 * w0.y; aA[2] += x0 * w0.z; aA[3] += x0 * w0.w;
        aB[0] += x1 * w1.x; aB[1] += x1 * w1.y; aB[2] += x1 * w1.z; aB[3] += x1 * w1.w;
    }
    float acc[4];
#pragma unroll
    for (int c = 0; c < 4; c++) acc[c] = aA[c] + aB[c];

#pragma unroll
    for (int c = 0; c < 4; c++) hTs[(4 * cg + c) * 20 + rg] = f2h(acc[c]);

    const float4 a1v = ((const float4*)a1)[cg];
    const float4 a2v = ((const float4*)a2)[cg];
    float v1 = acc[0] * a1v.x + acc[1] * a1v.y + acc[2] * a1v.z + acc[3] * a1v.w;
    float v2 = acc[0] * a2v.x + acc[1] * a2v.y + acc[2] * a2v.z + acc[3] * a2v.w;
#pragma unroll
    for (int s = 8; s > 0; s >>= 1) {
        v1 += __shfl_xor_sync(0xffffffffu, v1, s, 16);
        v2 += __shfl_xor_sync(0xffffffffu, v2, s, 16);
    }

    const float s1L = v1 * LOG2E;
    const float s2L = v2 * LOG2E;
    const float E1 = ex2f(s1L), F1 = ex2f(ALPHA * s1L);
    const float E2 = ex2f(s2L), F2 = ex2f(ALPHA * s2L);
    const float E2o = __shfl_xor_sync(0xffffffffu, E2, 16);
    const float F2o = __shfl_xor_sync(0xffffffffu, F2, 16);
    if (cg == 0) {
        g_EF1p[i0 + rg] = make_uint2(pkh2(E1, E1), pkh2(F1, F1));
        if ((tid & 31) == 0)
            g_E2Fp[(i0 + rg) >> 1] = make_uint2(pkh2(E2, E2o), pkh2(F2, F2o));
    }
    __syncthreads();

    {
        const int f = tid >> 2;
        const int sg = tid & 3;
        const uint2 v = *(const uint2*)&hTs[f * 20 + 4 * sg];
        *(uint2*)(g_hT16 + (size_t)f * NN + i0 + 4 * sg) = v;
    }
}

// ===================== K2: warp-specialized fused GAT =====================
__global__ __launch_bounds__(NTHREADS, 1) void k_gat(const int* __restrict__ A,
                                                     float* __restrict__ out) {
    extern __shared__ char sm[];
    const uint32_t sb0 = smem_u32(sm);
    const uint32_t sb = (sb0 + 127u) & ~127u;
    const uint32_t mb = sb + MBAR_OFF;        // full[s]=mb+s*16, empty[s]=mb+s*16+8

    const int tid  = threadIdx.x;
    const int wid  = tid >> 5;
    const int lane = tid & 31;
    const int ib   = blockIdx.x >> 1;
    const int sk   = blockIdx.x & 1;
    const int i0   = ib * TI;
    const int j0   = sk * JH;

    if (tid == 0) {
#pragma unroll
        for (int s = 0; s < NSTAGE; s++) {
            MBAR_INIT(mb + s * 16,     64);   // full: 64 producer threads
            MBAR_INIT(mb + s * 16 + 8, 8);    // empty: 8 consumer warps
        }
    }
    __syncthreads();

    if (wid >= 8) {
        // ================= PRODUCER (2 warps, 64 threads) =================
        const int p = tid - 256;                  // 0..63
        const int ar = p >> 3;                    // A row group base (0..7)
        const int asg = p & 7;                    // A 16B segment
        const int* aSrc = A + (size_t)(i0) * NN + j0;
        const uint16_t* hSrc = g_hT16 + j0;

        for (int t = 0; t < NCH; t++) {
            const int s = t & (NSTAGE - 1);
            const int k = t >> 3;
            if (k > 0) MBAR_WAIT(mb + s * 16 + 8, (k - 1) & 1);

            const uint32_t base = sb + (uint32_t)(s * STAGE_BYTES);
            const int jo = t * KC;
            // A: 128 rows x 128B; thread covers rows ar+8*i, segment asg
#pragma unroll
            for (int i = 0; i < 16; i++) {
                const int r = ar + 8 * i;
                CP16(base + (uint32_t)(r * A_STRIDE + asg * 4) * 4,
                     aSrc + (size_t)r * NN + jo + asg * 4);
            }
            // B: 64 f-rows x 64B; thread p -> f row p, 4 segments
#pragma unroll
            for (int g = 0; g < 4; g++) {
                CP16(base + A_BUF + (uint32_t)(p * B_STRIDE + g * 8) * 2,
                     hSrc + (size_t)p * NN + jo + g * 8);
            }
            // EF: 128B
            if (p < 8)
                CP16(base + A_BUF + B_BUF + (uint32_t)p * 16,
                     g_E2Fp + ((j0 + jo) >> 1) + p * 2);
            CPASYNC_MBAR_ARRIVE(mb + s * 16);
        }
    } else {
        // ================= CONSUMER (8 warps) =================
        const int qr = lane >> 2;
        const int qc = lane & 3;
        const int mg = wid >> 1;
        const int ng = wid & 1;

        uint32_t e1E[4], e1F[4];
#pragma unroll
        for (int k = 0; k < 4; k++) {
            const uint2 v = g_EF1p[i0 + mg * 32 + qr + 8 * k];
            e1E[k] = v.x; e1F[k] = v.y;
        }

        float acc[2][4][4];
        float accO[2][4];
#pragma unroll
        for (int mt = 0; mt < 2; mt++) {
#pragma unroll
            for (int nt = 0; nt < 4; nt++)
#pragma unroll
                for (int k = 0; k < 4; k++) acc[mt][nt][k] = 0.f;
#pragma unroll
            for (int k = 0; k < 4; k++) accO[mt][k] = 0.f;
        }
        const uint32_t kOnes = 0x3C003C00u;

        for (int t = 0; t < NCH; t++) {
            const int s = t & (NSTAGE - 1);
            const int k = t >> 3;
            MBAR_WAIT(mb + s * 16, k & 1);

            const uint32_t aB = sb + (uint32_t)(s * STAGE_BYTES);
            const uint32_t bB = aB + A_BUF;
            const uint32_t eB = aB + A_BUF + B_BUF;

#pragma unroll
            for (int ks = 0; ks < 2; ks++) {
                const int j2 = 16 * ks + 2 * qc;
                const uint2 efL = lds_u64(eB + (uint32_t)(j2 >> 1) * 8);
                const uint2 efH = lds_u64(eB + (uint32_t)((j2 + 8) >> 1) * 8);

                uint32_t b0[4], b1[4];
#pragma unroll
                for (int nt = 0; nt < 4; nt++) {
                    const int f = ng * 32 + nt * 8 + qr;
                    const uint32_t hb = bB + (uint32_t)(f * B_STRIDE + j2) * 2;
                    b0[nt] = lds_u32(hb);
                    b1[nt] = lds_u32(hb + 16);
                }

#pragma unroll
                for (int mt = 0; mt < 2; mt++) {
                    const int r0 = mg * 32 + mt * 16 + qr;
                    const uint32_t ab = aB + (uint32_t)(r0 * A_STRIDE + j2) * 4;
                    const int2 Al0 = lds_s64(ab);
                    const int2 Ah0 = lds_s64(ab + 32);
                    const int2 Al1 = lds_s64(ab + (uint32_t)(8 * A_STRIDE) * 4);
                    const int2 Ah1 = lds_s64(ab + (uint32_t)(8 * A_STRIDE) * 4 + 32);

                    const uint32_t a0 = wpair(e1E[2*mt],   e1F[2*mt],   efL.x, efL.y, Al0.x, Al0.y);
                    const uint32_t a1 = wpair(e1E[2*mt+1], e1F[2*mt+1], efL.x, efL.y, Al1.x, Al1.y);
                    const uint32_t a2 = wpair(e1E[2*mt],   e1F[2*mt],   efH.x, efH.y, Ah0.x, Ah0.y);
                    const uint32_t a3 = wpair(e1E[2*mt+1], e1F[2*mt+1], efH.x, efH.y, Ah1.x, Ah1.y);

#pragma unroll
                    for (int nt = 0; nt < 4; nt++)
                        MMA_F16(acc[mt][nt], a0, a1, a2, a3, b0[nt], b1[nt]);
                    MMA_F16(accO[mt], a0, a1, a2, a3, kOnes, kOnes);
                }
            }
            __syncwarp();
            if (lane == 0) MBAR_ARRIVE(mb + s * 16 + 8);
        }

        // ---- epilogue: store partials ----
        if (ng == 0 && qc == 0) {
            g_wsum[sk][i0 + mg * 32 + qr]      = accO[0][0];
            g_wsum[sk][i0 + mg * 32 + qr + 8]  = accO[0][2];
            g_wsum[sk][i0 + mg * 32 + qr + 16] = accO[1][0];
            g_wsum[sk][i0 + mg * 32 + qr + 24] = accO[1][2];
        }
#pragma unroll
        for (int mt = 0; mt < 2; mt++) {
            float* pr0 = &g_part[sk][(size_t)(i0 + mg * 32 + mt * 16 + qr) * FOUT];
            float* pr1 = &g_part[sk][(size_t)(i0 + mg * 32 + mt * 16 + qr + 8) * FOUT];
#pragma unroll
            for (int nt = 0; nt < 4; nt++) {
                const int c0 = ng * 32 + nt * 8 + 2 * qc;
                *(float2*)(pr0 + c0) = make_float2(acc[mt][nt][0], acc[mt][nt][1]);
                *(float2*)(pr1 + c0) = make_float2(acc[mt][nt][2], acc[mt][nt][3]);
            }
        }
    }

    // ---- last split-K CTA for this i-block combines and divides ----
    __threadfence();
    __syncthreads();
    __shared__ int isLast;
    if (tid == 0) isLast = (atomicAdd(&g_cnt[ib], 1) == SPLIT - 1) ? 1 : 0;
    __syncthreads();
    if (isLast && tid < 256) {
        __threadfence();
#pragma unroll
        for (int k = 0; k < 8; k++) {
            const int idx4 = tid + k * 256;
            const int row = idx4 >> 4;
            const size_t e = (size_t)(i0 + row) * FOUT + (idx4 & 15) * 4;
            float4 s = *(const float4*)&g_part[0][e];
            float den = g_wsum[0][i0 + row];
#pragma unroll
            for (int p = 1; p < SPLIT; p++) {
                const float4 pp = *(const float4*)&g_part[p][e];
                s.x += pp.x; s.y += pp.y; s.z += pp.z; s.w += pp.w;
                den += g_wsum[p][i0 + row];
            }
            const float inv = 1.0f / den;
            *(float4*)(out + e) = make_float4(s.x * inv, s.y * inv, s.z * inv, s.w * inv);
        }
    }
}

extern "C" void kernel_launch(void* const* d_in, const int* in_sizes, int n_in,
                              void* d_out, int out_size) {
    const float* X  = (const float*)d_in[0];
    const int*   A  = (const int*)d_in[1];
    const float* W  = (const float*)d_in[2];
    const float* a1 = (const float*)d_in[3];
    const float* a2 = (const float*)d_in[4];
    float* out = (float*)d_out;

    cudaFuncSetAttribute(k_gat, cudaFuncAttributeMaxDynamicSharedMemorySize, GAT_SMEM);

    k_proj<<<NN / 16, 256>>>(X, W, a1, a2);
    k_gat<<<(NN / TI) * SPLIT, NTHREADS, GAT_SMEM>>>(A, out);
}

// round 11
// speedup vs baseline: 1.8592x; 1.0976x over previous
#include <cuda_runtime.h>
#include <cstdint>

#define NN    8192
#define FIN   128
#define FOUT  64
#define ALPHA 0.2f
#define LOG2E 1.4426950408889634f

#define TI    128
#define SPLIT 4
#define JH    (NN/SPLIT)   // 2048
#define KC    32
#define NCH   (JH/KC)      // 64
#define NSTAGE 4
#define NSTAGE_LOG2 2

#define NTHREADS 320       // 8 consumer warps + 2 producer warps

#define A_STRIDE 40        // ints per A row (32 + pad) -> 160B
#define B_STRIDE 40        // halves per B row (32 + pad) -> 80B
#define A_BUF  (TI*A_STRIDE*4)          // 20480
#define B_BUF  (FOUT*B_STRIDE*2)        // 5120
#define EF_BUF 256                      // 128 used
#define STAGE_BYTES (A_BUF + B_BUF + EF_BUF)   // 25856
#define MBAR_OFF   (NSTAGE*STAGE_BYTES)        // 103424
#define GAT_SMEM   (MBAR_OFF + NSTAGE*16 + 256)

// ---------------- device scratch ----------------
__device__ __align__(256) uint16_t g_hT16[(size_t)FOUT * NN];  // h^T fp16 [f][node]
__device__ __align__(256) uint2 g_EF1p[NN];     // {E1 dup f16x2, F1 dup f16x2}
__device__ __align__(256) uint2 g_E2Fp[NN/2];   // {E2 pair f16x2, F2 pair f16x2}
__device__ float  g_part[SPLIT][(size_t)NN * FOUT];
__device__ float  g_wsum[SPLIT][NN];
__device__ int    g_cnt[NN / TI];

// ---------------- helpers ----------------
__device__ __forceinline__ float ex2f(float x) {
    float r; asm("ex2.approx.ftz.f32 %0, %1;" : "=f"(r) : "f"(x)); return r;
}
__device__ __forceinline__ uint32_t smem_u32(const void* p) {
    uint32_t a;
    asm("{ .reg .u64 t; cvta.to.shared.u64 t, %1; cvt.u32.u64 %0, t; }" : "=r"(a) : "l"(p));
    return a;
}
__device__ __forceinline__ uint16_t f2h(float x) {
    uint16_t r; asm("cvt.rn.f16.f32 %0, %1;" : "=h"(r) : "f"(x)); return r;
}
__device__ __forceinline__ uint32_t pkh2(float lo, float hi) {
    uint32_t r; asm("cvt.rn.f16x2.f32 %0, %1, %2;" : "=r"(r) : "f"(hi), "f"(lo)); return r;
}
__device__ __forceinline__ uint32_t hmul2(uint32_t a, uint32_t b) {
    uint32_t r; asm("mul.f16x2 %0, %1, %2;" : "=r"(r) : "r"(a), "r"(b)); return r;
}
__device__ __forceinline__ uint32_t hmax2(uint32_t a, uint32_t b) {
    uint32_t r; asm("max.f16x2 %0, %1, %2;" : "=r"(r) : "r"(a), "r"(b)); return r;
}
__device__ __forceinline__ uint32_t wpair(uint32_t e1E, uint32_t e1F,
                                          uint32_t e2, uint32_t f2,
                                          int ax, int ay) {
    const uint32_t m = (uint32_t)ax * 0x3C00u + (uint32_t)ay * 0x3C000000u;
    return hmul2(hmax2(hmul2(e1E, e2), hmul2(e1F, f2)), m);
}

#define CP16(dst, src) \
    asm volatile("cp.async.cg.shared.global [%0], [%1], 16;" :: "r"(dst), "l"(src) : "memory")

// mbarrier ops
#define MBAR_INIT(mb, cnt) \
    asm volatile("mbarrier.init.shared.b64 [%0], %1;" :: "r"((uint32_t)(mb)), "r"((uint32_t)(cnt)) : "memory")
#define MBAR_ARRIVE(mb) \
    asm volatile("mbarrier.arrive.shared.b64 _, [%0];" :: "r"((uint32_t)(mb)) : "memory")
#define CPASYNC_MBAR_ARRIVE(mb) \
    asm volatile("cp.async.mbarrier.arrive.noinc.shared.b64 [%0];" :: "r"((uint32_t)(mb)) : "memory")
#define MBAR_WAIT(mb, parity) do { \
    uint32_t _m = (uint32_t)(mb); uint32_t _p = (uint32_t)(parity); uint32_t _d; \
    asm volatile("{\n\t.reg .pred p;\n\tmbarrier.try_wait.parity.shared.b64 p, [%1], %2;\n\tselp.b32 %0, 1, 0, p;\n\t}" \
        : "=r"(_d) : "r"(_m), "r"(_p) : "memory"); \
    if (!_d) { \
        asm volatile("{\n\t.reg .pred P1;\n\tWL_%=:\n\tmbarrier.try_wait.parity.shared.b64 P1, [%0], %1;\n\t@P1 bra.uni WD_%=;\n\tbra.uni WL_%=;\n\tWD_%=:\n\t}" \
            :: "r"(_m), "r"(_p) : "memory"); \
    } } while (0)

__device__ __forceinline__ uint32_t lds_u32(uint32_t a) {
    uint32_t v; asm volatile("ld.shared.b32 %0, [%1];" : "=r"(v) : "r"(a)); return v;
}
__device__ __forceinline__ int2 lds_s64(uint32_t a) {
    int2 v; asm volatile("ld.shared.v2.u32 {%0,%1}, [%2];" : "=r"(v.x), "=r"(v.y) : "r"(a)); return v;
}
__device__ __forceinline__ uint2 lds_u64(uint32_t a) {
    uint2 v; asm volatile("ld.shared.v2.u32 {%0,%1}, [%2];" : "=r"(v.x), "=r"(v.y) : "r"(a)); return v;
}

#define MMA_F16(c, a0, a1, a2, a3, b0, b1) \
    asm volatile("mma.sync.aligned.m16n8k16.row.col.f32.f16.f16.f32 " \
        "{%0,%1,%2,%3}, {%4,%5,%6,%7}, {%8,%9}, {%0,%1,%2,%3};" \
        : "+f"((c)[0]), "+f"((c)[1]), "+f"((c)[2]), "+f"((c)[3]) \
        : "r"(a0), "r"(a1), "r"(a2), "r"(a3), "r"(b0), "r"(b1))

// ===================== K1: projection + node tables + counter reset =====================
__global__ __launch_bounds__(256) void k_proj(const float* __restrict__ X,
                                              const float* __restrict__ W,
                                              const float* __restrict__ a1,
                                              const float* __restrict__ a2) {
    __shared__ float Ws[FIN * FOUT];
    __shared__ float Xs[FIN * 17];
    __shared__ uint16_t hTs[FOUT * 20];

    const int tid = threadIdx.x;
    const int i0 = blockIdx.x * 16;

    if (blockIdx.x == 0 && tid < NN / TI) g_cnt[tid] = 0;

    {
        const float4* W4 = (const float4*)W;
        float4* Ws4 = (float4*)Ws;
#pragma unroll
        for (int k = 0; k < 8; k++) Ws4[tid + k * 256] = W4[tid + k * 256];
    }
    {
        const int row = tid & 15;
        const int q0 = tid >> 4;
#pragma unroll
        for (int m = 0; m < 2; m++) {
            const int q = q0 + 16 * m;
            const float4 v = *(const float4*)(X + (size_t)(i0 + row) * FIN + 4 * q);
            Xs[(4 * q + 0) * 17 + row] = v.x;
            Xs[(4 * q + 1) * 17 + row] = v.y;
            Xs[(4 * q + 2) * 17 + row] = v.z;
            Xs[(4 * q + 3) * 17 + row] = v.w;
        }
    }
    __syncthreads();

    const int rg = tid >> 4;
    const int cg = tid & 15;
    const float4* Ws4 = (const float4*)Ws;

    float aA[4] = {0.f, 0.f, 0.f, 0.f}, aB[4] = {0.f, 0.f, 0.f, 0.f};
#pragma unroll 8
    for (int k = 0; k < FIN; k += 2) {
        const float x0 = Xs[k * 17 + rg];
        const float x1 = Xs[(k + 1) * 17 + rg];
        const float4 w0 = Ws4[k * 16 + cg];
        const float4 w1 = Ws4[(k + 1) * 16 + cg];
        aA[0] += x0 * w0.x; aA[1] += x0 * w0.y; aA[2] += x0 * w0.z; aA[3] += x0 * w0.w;
        aB[0] += x1 * w1.x; aB[1] += x1 * w1.y; aB[2] += x1 * w1.z; aB[3] += x1 * w1.w;
    }
    float acc[4];
#pragma unroll
    for (int c = 0; c < 4; c++) acc[c] = aA[c] + aB[c];

#pragma unroll
    for (int c = 0; c < 4; c++) hTs[(4 * cg + c) * 20 + rg] = f2h(acc[c]);

    const float4 a1v = ((const float4*)a1)[cg];
    const float4 a2v = ((const float4*)a2)[cg];
    float v1 = acc[0] * a1v.x + acc[1] * a1v.y + acc[2] * a1v.z + acc[3] * a1v.w;
    float v2 = acc[0] * a2v.x + acc[1] * a2v.y + acc[2] * a2v.z + acc[3] * a2v.w;
#pragma unroll
    for (int s = 8; s > 0; s >>= 1) {
        v1 += __shfl_xor_sync(0xffffffffu, v1, s, 16);
        v2 += __shfl_xor_sync(0xffffffffu, v2, s, 16);
    }

    const float s1L = v1 * LOG2E;
    const float s2L = v2 * LOG2E;
    const float E1 = ex2f(s1L), F1 = ex2f(ALPHA * s1L);
    const float E2 = ex2f(s2L), F2 = ex2f(ALPHA * s2L);
    const float E2o = __shfl_xor_sync(0xffffffffu, E2, 16);
    const float F2o = __shfl_xor_sync(0xffffffffu, F2, 16);
    if (cg == 0) {
        g_EF1p[i0 + rg] = make_uint2(pkh2(E1, E1), pkh2(F1, F1));
        if ((tid & 31) == 0)
            g_E2Fp[(i0 + rg) >> 1] = make_uint2(pkh2(E2, E2o), pkh2(F2, F2o));
    }
    __syncthreads();

    {
        const int f = tid >> 2;
        const int sg = tid & 3;
        const uint2 v = *(const uint2*)&hTs[f * 20 + 4 * sg];
        *(uint2*)(g_hT16 + (size_t)f * NN + i0 + 4 * sg) = v;
    }
}

// ===================== K2: warp-specialized fused GAT (2 CTAs/SM) =====================
__global__ __launch_bounds__(NTHREADS, 2) void k_gat(const int* __restrict__ A,
                                                     float* __restrict__ out) {
    extern __shared__ char sm[];
    const uint32_t sb0 = smem_u32(sm);
    const uint32_t sb = (sb0 + 127u) & ~127u;
    const uint32_t mb = sb + MBAR_OFF;        // full[s]=mb+s*16, empty[s]=mb+s*16+8

    const int tid  = threadIdx.x;
    const int wid  = tid >> 5;
    const int lane = tid & 31;
    const int ib   = blockIdx.x >> 2;
    const int sk   = blockIdx.x & 3;
    const int i0   = ib * TI;
    const int j0   = sk * JH;

    if (tid == 0) {
#pragma unroll
        for (int s = 0; s < NSTAGE; s++) {
            MBAR_INIT(mb + s * 16,     64);   // full: 64 producer threads
            MBAR_INIT(mb + s * 16 + 8, 8);    // empty: 8 consumer warps
        }
    }
    __syncthreads();

    if (wid >= 8) {
        // ================= PRODUCER (2 warps, 64 threads) =================
        const int p = tid - 256;                  // 0..63
        const int ar = p >> 3;                    // A row group base (0..7)
        const int asg = p & 7;                    // A 16B segment
        const int* aSrc = A + (size_t)(i0) * NN + j0;
        const uint16_t* hSrc = g_hT16 + j0;

        for (int t = 0; t < NCH; t++) {
            const int s = t & (NSTAGE - 1);
            const int k = t >> NSTAGE_LOG2;
            if (k > 0) MBAR_WAIT(mb + s * 16 + 8, (k - 1) & 1);

            const uint32_t base = sb + (uint32_t)(s * STAGE_BYTES);
            const int jo = t * KC;
#pragma unroll
            for (int i = 0; i < 16; i++) {
                const int r = ar + 8 * i;
                CP16(base + (uint32_t)(r * A_STRIDE + asg * 4) * 4,
                     aSrc + (size_t)r * NN + jo + asg * 4);
            }
#pragma unroll
            for (int g = 0; g < 4; g++) {
                CP16(base + A_BUF + (uint32_t)(p * B_STRIDE + g * 8) * 2,
                     hSrc + (size_t)p * NN + jo + g * 8);
            }
            if (p < 8)
                CP16(base + A_BUF + B_BUF + (uint32_t)p * 16,
                     g_E2Fp + ((j0 + jo) >> 1) + p * 2);
            CPASYNC_MBAR_ARRIVE(mb + s * 16);
        }
    } else {
        // ================= CONSUMER (8 warps) =================
        const int qr = lane >> 2;
        const int qc = lane & 3;
        const int mg = wid >> 1;
        const int ng = wid & 1;

        uint32_t e1E[4], e1F[4];
#pragma unroll
        for (int k = 0; k < 4; k++) {
            const uint2 v = g_EF1p[i0 + mg * 32 + qr + 8 * k];
            e1E[k] = v.x; e1F[k] = v.y;
        }

        float acc[2][4][4];
        float accO[2][4];
#pragma unroll
        for (int mt = 0; mt < 2; mt++) {
#pragma unroll
            for (int nt = 0; nt < 4; nt++)
#pragma unroll
                for (int k = 0; k < 4; k++) acc[mt][nt][k] = 0.f;
#pragma unroll
            for (int k = 0; k < 4; k++) accO[mt][k] = 0.f;
        }
        const uint32_t kOnes = 0x3C003C00u;

        for (int t = 0; t < NCH; t++) {
            const int s = t & (NSTAGE - 1);
            const int k = t >> NSTAGE_LOG2;
            MBAR_WAIT(mb + s * 16, k & 1);

            const uint32_t aB = sb + (uint32_t)(s * STAGE_BYTES);
            const uint32_t bB = aB + A_BUF;
            const uint32_t eB = aB + A_BUF + B_BUF;

#pragma unroll
            for (int ks = 0; ks < 2; ks++) {
                const int j2 = 16 * ks + 2 * qc;
                const uint2 efL = lds_u64(eB + (uint32_t)(j2 >> 1) * 8);
                const uint2 efH = lds_u64(eB + (uint32_t)((j2 + 8) >> 1) * 8);

                uint32_t b0[4], b1[4];
#pragma unroll
                for (int nt = 0; nt < 4; nt++) {
                    const int f = ng * 32 + nt * 8 + qr;
                    const uint32_t hb = bB + (uint32_t)(f * B_STRIDE + j2) * 2;
                    b0[nt] = lds_u32(hb);
                    b1[nt] = lds_u32(hb + 16);
                }

#pragma unroll
                for (int mt = 0; mt < 2; mt++) {
                    const int r0 = mg * 32 + mt * 16 + qr;
                    const uint32_t ab = aB + (uint32_t)(r0 * A_STRIDE + j2) * 4;
                    const int2 Al0 = lds_s64(ab);
                    const int2 Ah0 = lds_s64(ab + 32);
                    const int2 Al1 = lds_s64(ab + (uint32_t)(8 * A_STRIDE) * 4);
                    const int2 Ah1 = lds_s64(ab + (uint32_t)(8 * A_STRIDE) * 4 + 32);

                    const uint32_t a0 = wpair(e1E[2*mt],   e1F[2*mt],   efL.x, efL.y, Al0.x, Al0.y);
                    const uint32_t a1 = wpair(e1E[2*mt+1], e1F[2*mt+1], efL.x, efL.y, Al1.x, Al1.y);
                    const uint32_t a2 = wpair(e1E[2*mt],   e1F[2*mt],   efH.x, efH.y, Ah0.x, Ah0.y);
                    const uint32_t a3 = wpair(e1E[2*mt+1], e1F[2*mt+1], efH.x, efH.y, Ah1.x, Ah1.y);

#pragma unroll
                    for (int nt = 0; nt < 4; nt++)
                        MMA_F16(acc[mt][nt], a0, a1, a2, a3, b0[nt], b1[nt]);
                    MMA_F16(accO[mt], a0, a1, a2, a3, kOnes, kOnes);
                }
            }
            __syncwarp();
            if (lane == 0) MBAR_ARRIVE(mb + s * 16 + 8);
        }

        // ---- epilogue: store partials ----
        if (ng == 0 && qc == 0) {
            g_wsum[sk][i0 + mg * 32 + qr]      = accO[0][0];
            g_wsum[sk][i0 + mg * 32 + qr + 8]  = accO[0][2];
            g_wsum[sk][i0 + mg * 32 + qr + 16] = accO[1][0];
            g_wsum[sk][i0 + mg * 32 + qr + 24] = accO[1][2];
        }
#pragma unroll
        for (int mt = 0; mt < 2; mt++) {
            float* pr0 = &g_part[sk][(size_t)(i0 + mg * 32 + mt * 16 + qr) * FOUT];
            float* pr1 = &g_part[sk][(size_t)(i0 + mg * 32 + mt * 16 + qr + 8) * FOUT];
#pragma unroll
            for (int nt = 0; nt < 4; nt++) {
                const int c0 = ng * 32 + nt * 8 + 2 * qc;
                *(float2*)(pr0 + c0) = make_float2(acc[mt][nt][0], acc[mt][nt][1]);
                *(float2*)(pr1 + c0) = make_float2(acc[mt][nt][2], acc[mt][nt][3]);
            }
        }
    }

    // ---- last split-K CTA for this i-block combines and divides ----
    __threadfence();
    __syncthreads();
    __shared__ int isLast;
    if (tid == 0) isLast = (atomicAdd(&g_cnt[ib], 1) == SPLIT - 1) ? 1 : 0;
    __syncthreads();
    if (isLast && tid < 256) {
        __threadfence();
#pragma unroll
        for (int k = 0; k < 8; k++) {
            const int idx4 = tid + k * 256;
            const int row = idx4 >> 4;
            const size_t e = (size_t)(i0 + row) * FOUT + (idx4 & 15) * 4;
            float4 s = *(const float4*)&g_part[0][e];
            float den = g_wsum[0][i0 + row];
#pragma unroll
            for (int p = 1; p < SPLIT; p++) {
                const float4 pp = *(const float4*)&g_part[p][e];
                s.x += pp.x; s.y += pp.y; s.z += pp.z; s.w += pp.w;
                den += g_wsum[p][i0 + row];
            }
            const float inv = 1.0f / den;
            *(float4*)(out + e) = make_float4(s.x * inv, s.y * inv, s.z * inv, s.w * inv);
        }
    }
}

extern "C" void kernel_launch(void* const* d_in, const int* in_sizes, int n_in,
                              void* d_out, int out_size) {
    const float* X  = (const float*)d_in[0];
    const int*   A  = (const int*)d_in[1];
    const float* W  = (const float*)d_in[2];
    const float* a1 = (const float*)d_in[3];
    const float* a2 = (const float*)d_in[4];
    float* out = (float*)d_out;

    cudaFuncSetAttribute(k_gat, cudaFuncAttributeMaxDynamicSharedMemorySize, GAT_SMEM);

    k_proj<<<NN / 16, 256>>>(X, W, a1, a2);
    k_gat<<<(NN / TI) * SPLIT, NTHREADS, GAT_SMEM>>>(A, out);
}